// round 13
// baseline (speedup 1.0000x reference)
#include <cuda_runtime.h>
#include <cuda_bf16.h>
#include <math.h>
#include <stdint.h>

#define BB 4
#define TT 1024
#define DD 1024
#define HH 16
#define HD 64

// softmax scale folded into Q: log2(e)/8
#define QSCALE 0.18033688011112042f

typedef unsigned long long ull;

// ---------------- scratch (device globals; no allocation allowed) ----------
__device__ float g_y [BB*HH*TT*HD];    // attention out (B,H,T,64) fp32
// bf16 split operands for the projection GEMMs
__device__ __nv_bfloat16 g_AH[4096*1024];
__device__ __nv_bfloat16 g_AL[4096*1024];
__device__ __nv_bfloat16 g_BH[3072*1024];   // transposed: [N,K]
__device__ __nv_bfloat16 g_BL[3072*1024];
// bf16 hi/lo attention operands, (B,H,T,64)
#define AELE (BB*HH*TT*HD)
__device__ __nv_bfloat16 g_q1h[AELE], g_q1l[AELE], g_q2h[AELE], g_q2l[AELE];
__device__ __nv_bfloat16 g_k1h[AELE], g_k1l[AELE], g_k2h[AELE], g_k2l[AELE];
__device__ __nv_bfloat16 g_vh [AELE], g_vl [AELE];

// =================== small asm helpers =====================================
__device__ __forceinline__ uint32_t s2u(const void* p) {
    uint32_t a;
    asm("{ .reg .u64 t; cvta.to.shared.u64 t, %1; cvt.u32.u64 %0, t; }" : "=r"(a) : "l"(p));
    return a;
}
__device__ __forceinline__ void cpa16(uint32_t d, const void* s) {
    asm volatile("cp.async.cg.shared.global [%0], [%1], 16;" :: "r"(d), "l"(s));
}
__device__ __forceinline__ void ldsm4(uint32_t* r, uint32_t a) {
    asm volatile("ldmatrix.sync.aligned.m8n8.x4.shared.b16 {%0,%1,%2,%3}, [%4];"
                 : "=r"(r[0]), "=r"(r[1]), "=r"(r[2]), "=r"(r[3]) : "r"(a));
}
__device__ __forceinline__ void ldsm4t(uint32_t* r, uint32_t a) {
    asm volatile("ldmatrix.sync.aligned.m8n8.x4.trans.shared.b16 {%0,%1,%2,%3}, [%4];"
                 : "=r"(r[0]), "=r"(r[1]), "=r"(r[2]), "=r"(r[3]) : "r"(a));
}
#define MMA_BF16(d, a, b)                                                     \
    asm volatile("mma.sync.aligned.m16n8k16.row.col.f32.bf16.bf16.f32 "       \
        "{%0,%1,%2,%3}, {%4,%5,%6,%7}, {%8,%9}, {%0,%1,%2,%3};"               \
        : "+f"((d)[0]), "+f"((d)[1]), "+f"((d)[2]), "+f"((d)[3])              \
        : "r"((a)[0]), "r"((a)[1]), "r"((a)[2]), "r"((a)[3]),                 \
          "r"((b)[0]), "r"((b)[1]))
__device__ __forceinline__ uint32_t swz(uint32_t bo) {
    return bo ^ ((bo >> 3) & 0x70);
}
__device__ __forceinline__ uint32_t pkhi(float a, float b) {
    uint32_t d;
    asm("prmt.b32 %0, %1, %2, 0x7632;" : "=r"(d)
        : "r"(__float_as_uint(a)), "r"(__float_as_uint(b)));
    return d;
}
__device__ __forceinline__ uint32_t pkbf2(float lo, float hi) {
    uint32_t d;
    asm("cvt.rn.bf16x2.f32 %0, %1, %2;" : "=r"(d) : "f"(hi), "f"(lo));
    return d;
}
__device__ __forceinline__ float trunclo(float f) {
    return f - __uint_as_float(__float_as_uint(f) & 0xFFFF0000u);
}
__device__ __forceinline__ float ex2(float x) {
    float y;
    asm("ex2.approx.f32 %0, %1;" : "=f"(y) : "f"(x));
    return y;
}

// =================== fp32 -> bf16 hi/lo split kernels ======================
__global__ void convA(const float* __restrict__ X, __nv_bfloat16* __restrict__ H,
                      __nv_bfloat16* __restrict__ L)
{
    int i = (blockIdx.x * 256 + threadIdx.x) * 4;
    float4 v = *(const float4*)(X + i);
    __nv_bfloat16 h0 = __float2bfloat16(v.x), h1 = __float2bfloat16(v.y);
    __nv_bfloat16 h2 = __float2bfloat16(v.z), h3 = __float2bfloat16(v.w);
    __nv_bfloat16 l0 = __float2bfloat16(v.x - __bfloat162float(h0));
    __nv_bfloat16 l1 = __float2bfloat16(v.y - __bfloat162float(h1));
    __nv_bfloat16 l2 = __float2bfloat16(v.z - __bfloat162float(h2));
    __nv_bfloat16 l3 = __float2bfloat16(v.w - __bfloat162float(h3));
    *(__nv_bfloat162*)(H + i)     = __nv_bfloat162(h0, h1);
    *(__nv_bfloat162*)(H + i + 2) = __nv_bfloat162(h2, h3);
    *(__nv_bfloat162*)(L + i)     = __nv_bfloat162(l0, l1);
    *(__nv_bfloat162*)(L + i + 2) = __nv_bfloat162(l2, l3);
}

__global__ void convBT(const float* __restrict__ W, __nv_bfloat16* __restrict__ H,
                       __nv_bfloat16* __restrict__ L, int K, int N)
{
    __shared__ float s[32][33];
    int nb = blockIdx.x * 32, kb = blockIdx.y * 32;
    int tx = threadIdx.x, ty = threadIdx.y;
#pragma unroll
    for (int i = 0; i < 4; i++)
        s[ty + i * 8][tx] = W[(size_t)(kb + ty + i * 8) * N + nb + tx];
    __syncthreads();
#pragma unroll
    for (int i = 0; i < 4; i++) {
        float v = s[tx][ty + i * 8];
        __nv_bfloat16 h = __float2bfloat16(v);
        __nv_bfloat16 l = __float2bfloat16(v - __bfloat162float(h));
        size_t o = (size_t)(nb + ty + i * 8) * K + kb + tx;
        H[o] = h; L[o] = l;
    }
}

// ============ bf16 split GEMM on mma.sync, templated epilogue ==============
// MODE 0: plain fp32 C store.
// MODE 1: fused per-head RMSNorm (x QSCALE) -> g_q{1,2}{h,l} head-major bf16.
// MODE 2: fused per-head RMSNorm -> g_k{1,2}{h,l}; part 2 = V copy -> g_v{h,l}.
#define MG_STAGE 65536
#define MG_TOTAL (2 * MG_STAGE)

template<int MODE>
__global__ __launch_bounds__(256, 1)
void mma_gemm(const __nv_bfloat16* __restrict__ Ah, const __nv_bfloat16* __restrict__ Al,
              const __nv_bfloat16* __restrict__ Bh, const __nv_bfloat16* __restrict__ Bl,
              float* __restrict__ C, const float* __restrict__ w1,
              const float* __restrict__ w2, int M, int N, int K)
{
    extern __shared__ char smem[];
    const uint32_t sb = s2u(smem);
    const int tid = threadIdx.x;
    const int wid = tid >> 5, lane = tid & 31;
    const int bx = blockIdx.x, by = blockIdx.y;
    const int wm = (wid & 3) * 32;
    const int wn = (wid >> 2) * 64;

    const __nv_bfloat16* pAh = Ah + (size_t)(by * 128) * K;
    const __nv_bfloat16* pAl = Al + (size_t)(by * 128) * K;
    const __nv_bfloat16* pBh = Bh + (size_t)(bx * 128) * K;
    const __nv_bfloat16* pBl = Bl + (size_t)(bx * 128) * K;

    const int NC = K >> 6;

    float acc[2][8][4];
#pragma unroll
    for (int mf = 0; mf < 2; mf++)
#pragma unroll
        for (int nf = 0; nf < 8; nf++)
#pragma unroll
            for (int q = 0; q < 4; q++) acc[mf][nf][q] = 0.f;

    auto issue = [&](int ch, int st) {
        uint32_t stb = sb + st * MG_STAGE;
        int k0 = ch << 6;
#pragma unroll
        for (int it = 0; it < 4; it++) {
            int idx = tid + it * 256;
            int row = idx >> 3, c8 = idx & 7;
            uint32_t so = swz(row * 128 + c8 * 16);
            size_t go = (size_t)row * K + k0 + c8 * 8;
            cpa16(stb + 0 * 16384 + so, pAh + go);
            cpa16(stb + 1 * 16384 + so, pAl + go);
            cpa16(stb + 2 * 16384 + so, pBh + go);
            cpa16(stb + 3 * 16384 + so, pBl + go);
        }
        asm volatile("cp.async.commit_group;" ::: "memory");
    };

    issue(0, 0);

    const int a_r  = lane & 15;
    const int a_kb = (lane >> 4) * 16;
    const int b_r  = (lane & 7) + ((lane >> 4) & 1) * 8;
    const int b_kb = ((lane >> 3) & 1) * 16;

    for (int ch = 0; ch < NC; ch++) {
        const int st = ch & 1;
        if (ch + 1 < NC) issue(ch + 1, st ^ 1);
        if (ch + 1 < NC)
            asm volatile("cp.async.wait_group 1;" ::: "memory");
        else
            asm volatile("cp.async.wait_group 0;" ::: "memory");
        __syncthreads();

        const uint32_t sAh = sb + st * MG_STAGE + 0 * 16384;
        const uint32_t sAl = sb + st * MG_STAGE + 1 * 16384;
        const uint32_t sBh = sb + st * MG_STAGE + 2 * 16384;
        const uint32_t sBl = sb + st * MG_STAGE + 3 * 16384;

#pragma unroll
        for (int ks = 0; ks < 4; ks++) {
            uint32_t aH[2][4], aL[2][4], bH[16], bL[16];
#pragma unroll
            for (int mf = 0; mf < 2; mf++) {
                uint32_t off = swz((wm + mf * 16 + a_r) * 128 + ks * 32 + a_kb);
                ldsm4(aH[mf], sAh + off);
                ldsm4(aL[mf], sAl + off);
            }
#pragma unroll
            for (int g = 0; g < 4; g++) {
                uint32_t off = swz((wn + g * 16 + b_r) * 128 + ks * 32 + b_kb);
                ldsm4(bH + g * 4, sBh + off);
                ldsm4(bL + g * 4, sBl + off);
            }
#pragma unroll
            for (int mf = 0; mf < 2; mf++)
#pragma unroll
                for (int nf = 0; nf < 8; nf++) {
                    MMA_BF16(acc[mf][nf], aH[mf], bH + nf * 2);
                    MMA_BF16(acc[mf][nf], aH[mf], bL + nf * 2);
                    MMA_BF16(acc[mf][nf], aL[mf], bH + nf * 2);
                }
        }
        __syncthreads();
    }

    const int er = lane >> 2, ec = (lane & 3) * 2;

    if (MODE == 0) {
#pragma unroll
        for (int mf = 0; mf < 2; mf++) {
#pragma unroll
            for (int nf = 0; nf < 8; nf++) {
                int row0 = by * 128 + wm + mf * 16 + er;
                int col  = bx * 128 + wn + nf * 8 + ec;
                float2 v0 = make_float2(acc[mf][nf][0], acc[mf][nf][1]);
                float2 v1 = make_float2(acc[mf][nf][2], acc[mf][nf][3]);
                *(float2*)(C + (size_t)row0 * N + col)       = v0;
                *(float2*)(C + (size_t)(row0 + 8) * N + col) = v1;
            }
        }
    } else {
        // ---- fused per-head RMSNorm epilogue ----
        const int gc   = bx * 128 + wn;        // 64-aligned global col base
        const int part = gc >> 10;             // MODE1: 0/1 (q1/q2); MODE2: 0/1/2
        const int hh   = (gc >> 6) & 15;
        const bool donorm = (MODE == 1) || (part < 2);
        const float* w = (part == 0) ? w1 : ((part == 1) ? w2 : (const float*)0);

        float wv[16];
        if (donorm) {
#pragma unroll
            for (int nf = 0; nf < 8; nf++) {
                wv[2 * nf]     = w[nf * 8 + ec];
                wv[2 * nf + 1] = w[nf * 8 + ec + 1];
            }
        }
        __nv_bfloat16 *dh, *dl;
        if (MODE == 1) { dh = part ? g_q2h : g_q1h; dl = part ? g_q2l : g_q1l; }
        else { dh = (part == 0) ? g_k1h : ((part == 1) ? g_k2h : g_vh);
               dl = (part == 0) ? g_k1l : ((part == 1) ? g_k2l : g_vl); }

#pragma unroll
        for (int mf = 0; mf < 2; mf++) {
            float s0 = 0.f, s1 = 0.f;
#pragma unroll
            for (int nf = 0; nf < 8; nf++) {
                s0 += acc[mf][nf][0] * acc[mf][nf][0] + acc[mf][nf][1] * acc[mf][nf][1];
                s1 += acc[mf][nf][2] * acc[mf][nf][2] + acc[mf][nf][3] * acc[mf][nf][3];
            }
            s0 += __shfl_xor_sync(0xffffffffu, s0, 1);
            s0 += __shfl_xor_sync(0xffffffffu, s0, 2);
            s1 += __shfl_xor_sync(0xffffffffu, s1, 1);
            s1 += __shfl_xor_sync(0xffffffffu, s1, 2);
            float in0 = 1.f, in1 = 1.f;
            if (donorm) {
                in0 = rsqrtf(s0 * (1.f / 64.f) + 1e-5f);
                in1 = rsqrtf(s1 * (1.f / 64.f) + 1e-5f);
                if (MODE == 1) { in0 *= QSCALE; in1 *= QSCALE; }
            }
            int r0 = by * 128 + wm + mf * 16 + er;
            int r1 = r0 + 8;
            size_t base0 = ((size_t)(((r0 >> 10) * 16 + hh) * 1024 + (r0 & 1023))) * 64;
            size_t base1 = ((size_t)(((r1 >> 10) * 16 + hh) * 1024 + (r1 & 1023))) * 64;
#pragma unroll
            for (int nf = 0; nf < 8; nf++) {
                int d = nf * 8 + ec;
                float v0 = acc[mf][nf][0] * in0, v1 = acc[mf][nf][1] * in0;
                float v2 = acc[mf][nf][2] * in1, v3 = acc[mf][nf][3] * in1;
                if (donorm) {
                    v0 *= wv[2 * nf]; v1 *= wv[2 * nf + 1];
                    v2 *= wv[2 * nf]; v3 *= wv[2 * nf + 1];
                }
                __nv_bfloat16 h0 = __float2bfloat16(v0), h1 = __float2bfloat16(v1);
                __nv_bfloat16 h2 = __float2bfloat16(v2), h3 = __float2bfloat16(v3);
                *(__nv_bfloat162*)(dh + base0 + d) = __nv_bfloat162(h0, h1);
                *(__nv_bfloat162*)(dh + base1 + d) = __nv_bfloat162(h2, h3);
                *(__nv_bfloat162*)(dl + base0 + d) = __nv_bfloat162(
                    __float2bfloat16(v0 - __bfloat162float(h0)),
                    __float2bfloat16(v1 - __bfloat162float(h1)));
                *(__nv_bfloat162*)(dl + base1 + d) = __nv_bfloat162(
                    __float2bfloat16(v2 - __bfloat162float(h2)),
                    __float2bfloat16(v3 - __bfloat162float(h3)));
            }
        }
    }
}

// ================= tensor-core differential flash attention ================
// CTA: 128 q-rows x one (b,h). 8 warps x 16 rows. KV chunks of 64 rows,
// SINGLE-buffered (112KB smem -> 2 CTAs/SM for latency hiding). K and V go
// in separate cp.async commit groups: QK runs after K lands while V is still
// in flight; PV waits for V. No online max; P = 2^(q·k·log2e/8).
// Trailing __syncthreads() before next chunk's issue is LOAD-BEARING (R7 race).
#define AT_SMEM (4 * 16384 + 6 * 8192)   // 114688 = 112KB

__global__ __launch_bounds__(256, 2)
void attn_mma(const float* __restrict__ lmb)
{
    extern __shared__ char smem[];
    const uint32_t sb = s2u(smem);
    const int tid = threadIdx.x;
    const int wid = tid >> 5, lane = tid & 31;
    const int qt = blockIdx.x, h = blockIdx.y, b = blockIdx.z;
    const size_t bh = (size_t)(b * HH + h) * (TT * HD);
    const int wm = wid * 16;
    const uint32_t kv0 = sb + 4 * 16384;

    // ---- Q tiles via cp.async (own commit group) ----
    {
        size_t qoff = bh + (size_t)qt * 128 * 64;
#pragma unroll
        for (int it = 0; it < 4; it++) {
            int idx = tid + it * 256;
            int row = idx >> 3, c8 = idx & 7;
            uint32_t so = swz(row * 128 + c8 * 16);
            size_t g = qoff + (size_t)row * 64 + c8 * 8;
            cpa16(sb + 0 * 16384 + so, g_q1h + g);
            cpa16(sb + 1 * 16384 + so, g_q1l + g);
            cpa16(sb + 2 * 16384 + so, g_q2h + g);
            cpa16(sb + 3 * 16384 + so, g_q2l + g);
        }
        asm volatile("cp.async.commit_group;" ::: "memory");
    }

    float o1[8][4], o2[8][4];
#pragma unroll
    for (int d = 0; d < 8; d++)
#pragma unroll
        for (int q = 0; q < 4; q++) { o1[d][q] = 0.f; o2[d][q] = 0.f; }
    float l1[2] = {0.f, 0.f}, l2[2] = {0.f, 0.f};   // per-thread partials

    const uint32_t a_off = (wm + (lane & 15)) * 128 + (lane >> 4) * 16;
    const uint32_t b_off = ((lane & 7) + ((lane >> 4) & 1) * 8) * 128
                         + ((lane >> 3) & 1) * 16;
    const uint32_t v_off = (lane & 15) * 128 + (lane >> 4) * 16;

    for (int kt = 0; kt < 16; kt++) {
        const size_t kbase = bh + (size_t)kt * 64 * 64;
        // ---- K group (4 arrays), then V group (2 arrays) ----
#pragma unroll
        for (int it = 0; it < 2; it++) {
            int idx = tid + it * 256;
            int row = idx >> 3, c8 = idx & 7;
            uint32_t so = swz(row * 128 + c8 * 16);
            size_t g = kbase + (size_t)row * 64 + c8 * 8;
            cpa16(kv0 + 0 * 8192 + so, g_k1h + g);
            cpa16(kv0 + 1 * 8192 + so, g_k1l + g);
            cpa16(kv0 + 2 * 8192 + so, g_k2h + g);
            cpa16(kv0 + 3 * 8192 + so, g_k2l + g);
        }
        asm volatile("cp.async.commit_group;" ::: "memory");
#pragma unroll
        for (int it = 0; it < 2; it++) {
            int idx = tid + it * 256;
            int row = idx >> 3, c8 = idx & 7;
            uint32_t so = swz(row * 128 + c8 * 16);
            size_t g = kbase + (size_t)row * 64 + c8 * 8;
            cpa16(kv0 + 4 * 8192 + so, g_vh + g);
            cpa16(kv0 + 5 * 8192 + so, g_vl + g);
        }
        asm volatile("cp.async.commit_group;" ::: "memory");

        // K (and Q on first iter) visible; V may still be in flight
        asm volatile("cp.async.wait_group 1;" ::: "memory");
        __syncthreads();

#pragma unroll
        for (int br = 0; br < 2; br++) {
            const uint32_t sAh = sb + (br ? 2 : 0) * 16384;
            const uint32_t sAl = sAh + 16384;
            const uint32_t sBh = kv0 + (br ? 2 : 0) * 8192;
            const uint32_t sBl = sBh + 8192;
            float* l = br ? l2 : l1;
            float (*o)[4] = br ? o2 : o1;

            // ---- S = Q K^T over 64 keys (3-product split) ----
            float sf[8][4];
#pragma unroll
            for (int nf = 0; nf < 8; nf++)
#pragma unroll
                for (int q = 0; q < 4; q++) sf[nf][q] = 0.f;
#pragma unroll
            for (int ks = 0; ks < 4; ks++) {
                uint32_t aH[4], aL[4];
                ldsm4(aH, sAh + swz(a_off + ks * 32));
                ldsm4(aL, sAl + swz(a_off + ks * 32));
#pragma unroll
                for (int g = 0; g < 4; g++) {
                    uint32_t bH[4], bL[4];
                    uint32_t off = swz(b_off + g * 2048 + ks * 32);
                    ldsm4(bH, sBh + off);
                    ldsm4(bL, sBl + off);
                    MMA_BF16(sf[2*g],   aH, bH);
                    MMA_BF16(sf[2*g],   aH, bL);
                    MMA_BF16(sf[2*g],   aL, bH);
                    MMA_BF16(sf[2*g+1], aH, bH + 2);
                    MMA_BF16(sf[2*g+1], aH, bL + 2);
                    MMA_BF16(sf[2*g+1], aL, bH + 2);
                }
            }

            // ---- P = 2^S ; accumulate per-thread l partials ----
            float p0 = 0.f, p1 = 0.f;
#pragma unroll
            for (int nf = 0; nf < 8; nf++) {
                sf[nf][0] = ex2(sf[nf][0]); p0 += sf[nf][0];
                sf[nf][1] = ex2(sf[nf][1]); p0 += sf[nf][1];
                sf[nf][2] = ex2(sf[nf][2]); p1 += sf[nf][2];
                sf[nf][3] = ex2(sf[nf][3]); p1 += sf[nf][3];
            }
            l[0] += p0; l[1] += p1;

            // ---- pack P fragments (bf16 hi/lo, A-layout) ----
            uint32_t ph[4][4], pl[4][4];
#pragma unroll
            for (int kf = 0; kf < 4; kf++) {
                float* f0 = sf[2*kf];
                float* f1 = sf[2*kf+1];
                ph[kf][0] = pkhi(f0[0], f0[1]);
                ph[kf][1] = pkhi(f0[2], f0[3]);
                ph[kf][2] = pkhi(f1[0], f1[1]);
                ph[kf][3] = pkhi(f1[2], f1[3]);
                pl[kf][0] = pkbf2(trunclo(f0[0]), trunclo(f0[1]));
                pl[kf][1] = pkbf2(trunclo(f0[2]), trunclo(f0[3]));
                pl[kf][2] = pkbf2(trunclo(f1[0]), trunclo(f1[1]));
                pl[kf][3] = pkbf2(trunclo(f1[2]), trunclo(f1[3]));
            }

            if (br == 0) {
                // V tile now needed: wait for its group, then sync
                asm volatile("cp.async.wait_group 0;" ::: "memory");
                __syncthreads();
            }

            // ---- O += P V (3-product split) ----
            const uint32_t sVh = kv0 + 4 * 8192;
            const uint32_t sVl = kv0 + 5 * 8192;
#pragma unroll
            for (int kf = 0; kf < 4; kf++) {
#pragma unroll
                for (int d2 = 0; d2 < 4; d2++) {
                    uint32_t vH[4], vL[4];
                    uint32_t off = swz(v_off + kf * 2048 + d2 * 32);
                    ldsm4t(vH, sVh + off);
                    ldsm4t(vL, sVl + off);
                    MMA_BF16(o[d2*2],   ph[kf], vH);
                    MMA_BF16(o[d2*2],   ph[kf], vL);
                    MMA_BF16(o[d2*2],   pl[kf], vH);
                    MMA_BF16(o[d2*2+1], ph[kf], vH + 2);
                    MMA_BF16(o[d2*2+1], ph[kf], vL + 2);
                    MMA_BF16(o[d2*2+1], pl[kf], vH + 2);
                }
            }
        }

        __syncthreads();   // all warps done with the buffer before refill
    }

    // ---- reduce l across quads (columns of each row) ----
#pragma unroll
    for (int off = 1; off <= 2; off <<= 1) {
        l1[0] += __shfl_xor_sync(0xffffffffu, l1[0], off);
        l1[1] += __shfl_xor_sync(0xffffffffu, l1[1], off);
        l2[0] += __shfl_xor_sync(0xffffffffu, l2[0], off);
        l2[1] += __shfl_xor_sync(0xffffffffu, l2[1], off);
    }

    // ---- epilogue: y = O1/l1 - softplus(lmb)·O2/l2 ----
    float cH = log1pf(__expf(lmb[h]));
    float i10 = 1.f / l1[0], i11 = 1.f / l1[1];
    float i20 = cH / l2[0],  i21 = cH / l2[1];
    const int er = lane >> 2, ec = (lane & 3) * 2;
#pragma unroll
    for (int d = 0; d < 8; d++) {
        size_t r0 = bh + (size_t)(qt * 128 + wm + er) * 64 + d * 8 + ec;
        size_t r1 = r0 + 8 * 64;
        float2 v0 = make_float2(o1[d][0] * i10 - o2[d][0] * i20,
                                o1[d][1] * i10 - o2[d][1] * i20);
        float2 v1 = make_float2(o1[d][2] * i11 - o2[d][2] * i21,
                                o1[d][3] * i11 - o2[d][3] * i21);
        *(float2*)(g_y + r0) = v0;
        *(float2*)(g_y + r1) = v1;
    }
}

// -------- GroupNorm per (b,h) over (T,HD); emits bf16 hi/lo split directly -
__global__ void groupnorm_kernel(const float* __restrict__ gn_w,
                                 const float* __restrict__ gn_b,
                                 __nv_bfloat16* __restrict__ AH,
                                 __nv_bfloat16* __restrict__ AL)
{
    __shared__ float rs[256], rq[256];
    const int bh = blockIdx.x;
    const float* src = g_y + (size_t)bh * TT * HD;
    const int tid = threadIdx.x;
    float s = 0.f, sq = 0.f;
    for (int i = tid; i < TT * HD; i += 256) {
        float v = src[i]; s += v; sq += v * v;
    }
    rs[tid] = s; rq[tid] = sq;
    __syncthreads();
    for (int off = 128; off > 0; off >>= 1) {
        if (tid < off) { rs[tid] += rs[tid + off]; rq[tid] += rq[tid + off]; }
        __syncthreads();
    }
    float mu  = rs[0] * (1.f / 65536.f);
    float var = rq[0] * (1.f / 65536.f) - mu * mu;
    float inv = rsqrtf(var + 1e-5f);
    int b = bh >> 4, h = bh & 15;
    for (int i = tid; i < TT * HD; i += 256) {
        int t = i >> 6, d = i & 63;
        float v = (src[i] - mu) * inv * gn_w[h * 64 + d] + gn_b[h * 64 + d];
        size_t o = (size_t)(b * TT + t) * DD + h * 64 + d;
        __nv_bfloat16 hi = __float2bfloat16(v);
        AH[o] = hi;
        AL[o] = __float2bfloat16(v - __bfloat162float(hi));
    }
}

// ---------------------------------------------------------------------------
extern "C" void kernel_launch(void* const* d_in, const int* in_sizes, int n_in,
                              void* d_out, int out_size)
{
    const float* x_q  = (const float*)d_in[0];
    const float* x_kv = (const float*)d_in[1];
    const float* Wq   = (const float*)d_in[2];
    const float* Wkv  = (const float*)d_in[3];
    const float* Wc   = (const float*)d_in[4];
    const float* qn1  = (const float*)d_in[5];
    const float* kn1  = (const float*)d_in[6];
    const float* qn2  = (const float*)d_in[7];
    const float* kn2  = (const float*)d_in[8];
    const float* gn_w = (const float*)d_in[9];
    const float* gn_b = (const float*)d_in[10];
    const float* lmb  = (const float*)d_in[11];
    float* out = (float*)d_out;
    (void)in_sizes; (void)n_in; (void)out_size;

    __nv_bfloat16 *AH, *AL, *BH, *BL;
    cudaGetSymbolAddress((void**)&AH, g_AH);
    cudaGetSymbolAddress((void**)&AL, g_AL);
    cudaGetSymbolAddress((void**)&BH, g_BH);
    cudaGetSymbolAddress((void**)&BL, g_BL);

    cudaFuncSetAttribute(mma_gemm<0>,
        cudaFuncAttributeMaxDynamicSharedMemorySize, MG_TOTAL);
    cudaFuncSetAttribute(mma_gemm<1>,
        cudaFuncAttributeMaxDynamicSharedMemorySize, MG_TOTAL);
    cudaFuncSetAttribute(mma_gemm<2>,
        cudaFuncAttributeMaxDynamicSharedMemorySize, MG_TOTAL);
    cudaFuncSetAttribute(attn_mma,
        cudaFuncAttributeMaxDynamicSharedMemorySize, AT_SMEM);

    // 1) q projections + fused per-head RMSNorm -> bf16 hi/lo head-major
    convA<<<4096, 256>>>(x_q, AH, AL);
    convBT<<<dim3(64, 32), dim3(32, 8)>>>(Wq, BH, BL, 1024, 2048);
    mma_gemm<1><<<dim3(16, 32), 256, MG_TOTAL>>>(AH, AL, BH, BL,
        (float*)0, qn1, qn2, 4096, 2048, 1024);
    // 2) kv projections + fused RMSNorm / V split
    convA<<<4096, 256>>>(x_kv, AH, AL);
    convBT<<<dim3(96, 32), dim3(32, 8)>>>(Wkv, BH, BL, 1024, 3072);
    mma_gemm<2><<<dim3(24, 32), 256, MG_TOTAL>>>(AH, AL, BH, BL,
        (float*)0, kn1, kn2, 4096, 3072, 1024);
    // 3) tensor-core differential flash attention (2 CTAs/SM)
    attn_mma<<<dim3(8, 16, 4), 256, AT_SMEM>>>(lmb);
    // 4) GroupNorm + relayout + bf16 split (fused)
    groupnorm_kernel<<<64, 256>>>(gn_w, gn_b, AH, AL);
    // 5) out = yt @ Wc
    convBT<<<dim3(32, 32), dim3(32, 8)>>>(Wc, BH, BL, 1024, 1024);
    mma_gemm<0><<<dim3(8, 32), 256, MG_TOTAL>>>(AH, AL, BH, BL,
        out, (float*)0, (float*)0, 4096, 1024, 1024);
}

// round 14
// speedup vs baseline: 1.1745x; 1.1745x over previous
#include <cuda_runtime.h>
#include <cuda_bf16.h>
#include <math.h>
#include <stdint.h>

#define BB 4
#define TT 1024
#define DD 1024
#define HH 16
#define HD 64

// softmax scale folded into Q: log2(e)/8
#define QSCALE 0.18033688011112042f

typedef unsigned long long ull;

// ---------------- scratch (device globals; no allocation allowed) ----------
__device__ float g_y [BB*HH*TT*HD];    // attention out (B,H,T,64) fp32
// bf16 split operands for the projection GEMMs
__device__ __nv_bfloat16 g_AH[4096*1024];
__device__ __nv_bfloat16 g_AL[4096*1024];
__device__ __nv_bfloat16 g_BH[3072*1024];   // transposed: [N,K]
__device__ __nv_bfloat16 g_BL[3072*1024];
// bf16 hi/lo attention operands, (B,H,T,64)
#define AELE (BB*HH*TT*HD)
__device__ __nv_bfloat16 g_q1h[AELE], g_q1l[AELE], g_q2h[AELE], g_q2l[AELE];
__device__ __nv_bfloat16 g_k1h[AELE], g_k1l[AELE], g_k2h[AELE], g_k2l[AELE];
__device__ __nv_bfloat16 g_vh [AELE], g_vl [AELE];

// =================== small asm helpers =====================================
__device__ __forceinline__ uint32_t s2u(const void* p) {
    uint32_t a;
    asm("{ .reg .u64 t; cvta.to.shared.u64 t, %1; cvt.u32.u64 %0, t; }" : "=r"(a) : "l"(p));
    return a;
}
__device__ __forceinline__ void cpa16(uint32_t d, const void* s) {
    asm volatile("cp.async.cg.shared.global [%0], [%1], 16;" :: "r"(d), "l"(s));
}
__device__ __forceinline__ void ldsm4(uint32_t* r, uint32_t a) {
    asm volatile("ldmatrix.sync.aligned.m8n8.x4.shared.b16 {%0,%1,%2,%3}, [%4];"
                 : "=r"(r[0]), "=r"(r[1]), "=r"(r[2]), "=r"(r[3]) : "r"(a));
}
__device__ __forceinline__ void ldsm4t(uint32_t* r, uint32_t a) {
    asm volatile("ldmatrix.sync.aligned.m8n8.x4.trans.shared.b16 {%0,%1,%2,%3}, [%4];"
                 : "=r"(r[0]), "=r"(r[1]), "=r"(r[2]), "=r"(r[3]) : "r"(a));
}
#define MMA_BF16(d, a, b)                                                     \
    asm volatile("mma.sync.aligned.m16n8k16.row.col.f32.bf16.bf16.f32 "       \
        "{%0,%1,%2,%3}, {%4,%5,%6,%7}, {%8,%9}, {%0,%1,%2,%3};"               \
        : "+f"((d)[0]), "+f"((d)[1]), "+f"((d)[2]), "+f"((d)[3])              \
        : "r"((a)[0]), "r"((a)[1]), "r"((a)[2]), "r"((a)[3]),                 \
          "r"((b)[0]), "r"((b)[1]))
__device__ __forceinline__ uint32_t swz(uint32_t bo) {
    return bo ^ ((bo >> 3) & 0x70);
}
__device__ __forceinline__ uint32_t pkhi(float a, float b) {
    uint32_t d;
    asm("prmt.b32 %0, %1, %2, 0x7632;" : "=r"(d)
        : "r"(__float_as_uint(a)), "r"(__float_as_uint(b)));
    return d;
}
__device__ __forceinline__ uint32_t pkbf2(float lo, float hi) {
    uint32_t d;
    asm("cvt.rn.bf16x2.f32 %0, %1, %2;" : "=r"(d) : "f"(hi), "f"(lo));
    return d;
}
__device__ __forceinline__ float trunclo(float f) {
    return f - __uint_as_float(__float_as_uint(f) & 0xFFFF0000u);
}
__device__ __forceinline__ float ex2(float x) {
    float y;
    asm("ex2.approx.f32 %0, %1;" : "=f"(y) : "f"(x));
    return y;
}

// =================== fp32 -> bf16 hi/lo split kernels ======================
__global__ void convA(const float* __restrict__ X, __nv_bfloat16* __restrict__ H,
                      __nv_bfloat16* __restrict__ L)
{
    int i = (blockIdx.x * 256 + threadIdx.x) * 4;
    float4 v = *(const float4*)(X + i);
    __nv_bfloat16 h0 = __float2bfloat16(v.x), h1 = __float2bfloat16(v.y);
    __nv_bfloat16 h2 = __float2bfloat16(v.z), h3 = __float2bfloat16(v.w);
    __nv_bfloat16 l0 = __float2bfloat16(v.x - __bfloat162float(h0));
    __nv_bfloat16 l1 = __float2bfloat16(v.y - __bfloat162float(h1));
    __nv_bfloat16 l2 = __float2bfloat16(v.z - __bfloat162float(h2));
    __nv_bfloat16 l3 = __float2bfloat16(v.w - __bfloat162float(h3));
    *(__nv_bfloat162*)(H + i)     = __nv_bfloat162(h0, h1);
    *(__nv_bfloat162*)(H + i + 2) = __nv_bfloat162(h2, h3);
    *(__nv_bfloat162*)(L + i)     = __nv_bfloat162(l0, l1);
    *(__nv_bfloat162*)(L + i + 2) = __nv_bfloat162(l2, l3);
}

__global__ void convBT(const float* __restrict__ W, __nv_bfloat16* __restrict__ H,
                       __nv_bfloat16* __restrict__ L, int K, int N)
{
    __shared__ float s[32][33];
    int nb = blockIdx.x * 32, kb = blockIdx.y * 32;
    int tx = threadIdx.x, ty = threadIdx.y;
#pragma unroll
    for (int i = 0; i < 4; i++)
        s[ty + i * 8][tx] = W[(size_t)(kb + ty + i * 8) * N + nb + tx];
    __syncthreads();
#pragma unroll
    for (int i = 0; i < 4; i++) {
        float v = s[tx][ty + i * 8];
        __nv_bfloat16 h = __float2bfloat16(v);
        __nv_bfloat16 l = __float2bfloat16(v - __bfloat162float(h));
        size_t o = (size_t)(nb + ty + i * 8) * K + kb + tx;
        H[o] = h; L[o] = l;
    }
}

// ============ bf16 split GEMM on mma.sync, templated epilogue ==============
// MODE 0: plain fp32 C store.
// MODE 1: fused per-head RMSNorm (x QSCALE) -> g_q{1,2}{h,l} head-major bf16.
// MODE 2: fused per-head RMSNorm -> g_k{1,2}{h,l}; part 2 = V copy -> g_v{h,l}.
#define MG_STAGE 65536
#define MG_TOTAL (2 * MG_STAGE)

template<int MODE>
__global__ __launch_bounds__(256, 1)
void mma_gemm(const __nv_bfloat16* __restrict__ Ah, const __nv_bfloat16* __restrict__ Al,
              const __nv_bfloat16* __restrict__ Bh, const __nv_bfloat16* __restrict__ Bl,
              float* __restrict__ C, const float* __restrict__ w1,
              const float* __restrict__ w2, int M, int N, int K)
{
    extern __shared__ char smem[];
    const uint32_t sb = s2u(smem);
    const int tid = threadIdx.x;
    const int wid = tid >> 5, lane = tid & 31;
    const int bx = blockIdx.x, by = blockIdx.y;
    const int wm = (wid & 3) * 32;
    const int wn = (wid >> 2) * 64;

    const __nv_bfloat16* pAh = Ah + (size_t)(by * 128) * K;
    const __nv_bfloat16* pAl = Al + (size_t)(by * 128) * K;
    const __nv_bfloat16* pBh = Bh + (size_t)(bx * 128) * K;
    const __nv_bfloat16* pBl = Bl + (size_t)(bx * 128) * K;

    const int NC = K >> 6;

    float acc[2][8][4];
#pragma unroll
    for (int mf = 0; mf < 2; mf++)
#pragma unroll
        for (int nf = 0; nf < 8; nf++)
#pragma unroll
            for (int q = 0; q < 4; q++) acc[mf][nf][q] = 0.f;

    auto issue = [&](int ch, int st) {
        uint32_t stb = sb + st * MG_STAGE;
        int k0 = ch << 6;
#pragma unroll
        for (int it = 0; it < 4; it++) {
            int idx = tid + it * 256;
            int row = idx >> 3, c8 = idx & 7;
            uint32_t so = swz(row * 128 + c8 * 16);
            size_t go = (size_t)row * K + k0 + c8 * 8;
            cpa16(stb + 0 * 16384 + so, pAh + go);
            cpa16(stb + 1 * 16384 + so, pAl + go);
            cpa16(stb + 2 * 16384 + so, pBh + go);
            cpa16(stb + 3 * 16384 + so, pBl + go);
        }
        asm volatile("cp.async.commit_group;" ::: "memory");
    };

    issue(0, 0);

    const int a_r  = lane & 15;
    const int a_kb = (lane >> 4) * 16;
    const int b_r  = (lane & 7) + ((lane >> 4) & 1) * 8;
    const int b_kb = ((lane >> 3) & 1) * 16;

    for (int ch = 0; ch < NC; ch++) {
        const int st = ch & 1;
        if (ch + 1 < NC) issue(ch + 1, st ^ 1);
        if (ch + 1 < NC)
            asm volatile("cp.async.wait_group 1;" ::: "memory");
        else
            asm volatile("cp.async.wait_group 0;" ::: "memory");
        __syncthreads();

        const uint32_t sAh = sb + st * MG_STAGE + 0 * 16384;
        const uint32_t sAl = sb + st * MG_STAGE + 1 * 16384;
        const uint32_t sBh = sb + st * MG_STAGE + 2 * 16384;
        const uint32_t sBl = sb + st * MG_STAGE + 3 * 16384;

#pragma unroll
        for (int ks = 0; ks < 4; ks++) {
            uint32_t aH[2][4], aL[2][4], bH[16], bL[16];
#pragma unroll
            for (int mf = 0; mf < 2; mf++) {
                uint32_t off = swz((wm + mf * 16 + a_r) * 128 + ks * 32 + a_kb);
                ldsm4(aH[mf], sAh + off);
                ldsm4(aL[mf], sAl + off);
            }
#pragma unroll
            for (int g = 0; g < 4; g++) {
                uint32_t off = swz((wn + g * 16 + b_r) * 128 + ks * 32 + b_kb);
                ldsm4(bH + g * 4, sBh + off);
                ldsm4(bL + g * 4, sBl + off);
            }
#pragma unroll
            for (int mf = 0; mf < 2; mf++)
#pragma unroll
                for (int nf = 0; nf < 8; nf++) {
                    MMA_BF16(acc[mf][nf], aH[mf], bH + nf * 2);
                    MMA_BF16(acc[mf][nf], aH[mf], bL + nf * 2);
                    MMA_BF16(acc[mf][nf], aL[mf], bH + nf * 2);
                }
        }
        __syncthreads();
    }

    const int er = lane >> 2, ec = (lane & 3) * 2;

    if (MODE == 0) {
#pragma unroll
        for (int mf = 0; mf < 2; mf++) {
#pragma unroll
            for (int nf = 0; nf < 8; nf++) {
                int row0 = by * 128 + wm + mf * 16 + er;
                int col  = bx * 128 + wn + nf * 8 + ec;
                float2 v0 = make_float2(acc[mf][nf][0], acc[mf][nf][1]);
                float2 v1 = make_float2(acc[mf][nf][2], acc[mf][nf][3]);
                *(float2*)(C + (size_t)row0 * N + col)       = v0;
                *(float2*)(C + (size_t)(row0 + 8) * N + col) = v1;
            }
        }
    } else {
        // ---- fused per-head RMSNorm epilogue ----
        const int gc   = bx * 128 + wn;        // 64-aligned global col base
        const int part = gc >> 10;             // MODE1: 0/1 (q1/q2); MODE2: 0/1/2
        const int hh   = (gc >> 6) & 15;
        const bool donorm = (MODE == 1) || (part < 2);
        const float* w = (part == 0) ? w1 : ((part == 1) ? w2 : (const float*)0);

        float wv[16];
        if (donorm) {
#pragma unroll
            for (int nf = 0; nf < 8; nf++) {
                wv[2 * nf]     = w[nf * 8 + ec];
                wv[2 * nf + 1] = w[nf * 8 + ec + 1];
            }
        }
        __nv_bfloat16 *dh, *dl;
        if (MODE == 1) { dh = part ? g_q2h : g_q1h; dl = part ? g_q2l : g_q1l; }
        else { dh = (part == 0) ? g_k1h : ((part == 1) ? g_k2h : g_vh);
               dl = (part == 0) ? g_k1l : ((part == 1) ? g_k2l : g_vl); }

#pragma unroll
        for (int mf = 0; mf < 2; mf++) {
            float s0 = 0.f, s1 = 0.f;
#pragma unroll
            for (int nf = 0; nf < 8; nf++) {
                s0 += acc[mf][nf][0] * acc[mf][nf][0] + acc[mf][nf][1] * acc[mf][nf][1];
                s1 += acc[mf][nf][2] * acc[mf][nf][2] + acc[mf][nf][3] * acc[mf][nf][3];
            }
            s0 += __shfl_xor_sync(0xffffffffu, s0, 1);
            s0 += __shfl_xor_sync(0xffffffffu, s0, 2);
            s1 += __shfl_xor_sync(0xffffffffu, s1, 1);
            s1 += __shfl_xor_sync(0xffffffffu, s1, 2);
            float in0 = 1.f, in1 = 1.f;
            if (donorm) {
                in0 = rsqrtf(s0 * (1.f / 64.f) + 1e-5f);
                in1 = rsqrtf(s1 * (1.f / 64.f) + 1e-5f);
                if (MODE == 1) { in0 *= QSCALE; in1 *= QSCALE; }
            }
            int r0 = by * 128 + wm + mf * 16 + er;
            int r1 = r0 + 8;
            size_t base0 = ((size_t)(((r0 >> 10) * 16 + hh) * 1024 + (r0 & 1023))) * 64;
            size_t base1 = ((size_t)(((r1 >> 10) * 16 + hh) * 1024 + (r1 & 1023))) * 64;
#pragma unroll
            for (int nf = 0; nf < 8; nf++) {
                int d = nf * 8 + ec;
                float v0 = acc[mf][nf][0] * in0, v1 = acc[mf][nf][1] * in0;
                float v2 = acc[mf][nf][2] * in1, v3 = acc[mf][nf][3] * in1;
                if (donorm) {
                    v0 *= wv[2 * nf]; v1 *= wv[2 * nf + 1];
                    v2 *= wv[2 * nf]; v3 *= wv[2 * nf + 1];
                }
                __nv_bfloat16 h0 = __float2bfloat16(v0), h1 = __float2bfloat16(v1);
                __nv_bfloat16 h2 = __float2bfloat16(v2), h3 = __float2bfloat16(v3);
                *(__nv_bfloat162*)(dh + base0 + d) = __nv_bfloat162(h0, h1);
                *(__nv_bfloat162*)(dh + base1 + d) = __nv_bfloat162(h2, h3);
                *(__nv_bfloat162*)(dl + base0 + d) = __nv_bfloat162(
                    __float2bfloat16(v0 - __bfloat162float(h0)),
                    __float2bfloat16(v1 - __bfloat162float(h1)));
                *(__nv_bfloat162*)(dl + base1 + d) = __nv_bfloat162(
                    __float2bfloat16(v2 - __bfloat162float(h2)),
                    __float2bfloat16(v3 - __bfloat162float(h3)));
            }
        }
    }
}

// ================= tensor-core differential flash attention ================
// CTA: 128 q-rows x one (b,h). 8 warps x 16 rows. KV chunks of 64 rows in a
// 3-STAGE ring: prefetch depth 2, ONE barrier per chunk. Stage-reuse distance
// of 3 + skew bound <1 iteration (the barrier) makes the R7 race impossible:
// issue(kt+2) targets the stage last read in chunk kt-1, which every warp has
// finished before passing sync(kt). No online max; P = 2^(q·k·log2e/8).
#define KVST 49152
#define AT_SMEM (4 * 16384 + 3 * KVST)   // 212992 = 208KB

__global__ __launch_bounds__(256, 1)
void attn_mma(const float* __restrict__ lmb)
{
    extern __shared__ char smem[];
    const uint32_t sb = s2u(smem);
    const int tid = threadIdx.x;
    const int wid = tid >> 5, lane = tid & 31;
    const int qt = blockIdx.x, h = blockIdx.y, b = blockIdx.z;
    const size_t bh = (size_t)(b * HH + h) * (TT * HD);
    const int wm = wid * 16;
    const uint32_t kv0 = sb + 4 * 16384;

    auto kvissue = [&](int kt) {
        uint32_t stb = kv0 + (kt % 3) * KVST;
        size_t kbase = bh + (size_t)kt * 64 * 64;
#pragma unroll
        for (int it = 0; it < 2; it++) {
            int idx = tid + it * 256;
            int row = idx >> 3, c8 = idx & 7;
            uint32_t so = swz(row * 128 + c8 * 16);
            size_t g = kbase + (size_t)row * 64 + c8 * 8;
            cpa16(stb + 0 * 8192 + so, g_k1h + g);
            cpa16(stb + 1 * 8192 + so, g_k1l + g);
            cpa16(stb + 2 * 8192 + so, g_k2h + g);
            cpa16(stb + 3 * 8192 + so, g_k2l + g);
            cpa16(stb + 4 * 8192 + so, g_vh + g);
            cpa16(stb + 5 * 8192 + so, g_vl + g);
        }
        asm volatile("cp.async.commit_group;" ::: "memory");
    };

    // ---- Q tiles (joins chunk 0's commit group), then chunks 0 and 1 ----
    {
        size_t qoff = bh + (size_t)qt * 128 * 64;
#pragma unroll
        for (int it = 0; it < 4; it++) {
            int idx = tid + it * 256;
            int row = idx >> 3, c8 = idx & 7;
            uint32_t so = swz(row * 128 + c8 * 16);
            size_t g = qoff + (size_t)row * 64 + c8 * 8;
            cpa16(sb + 0 * 16384 + so, g_q1h + g);
            cpa16(sb + 1 * 16384 + so, g_q1l + g);
            cpa16(sb + 2 * 16384 + so, g_q2h + g);
            cpa16(sb + 3 * 16384 + so, g_q2l + g);
        }
    }
    kvissue(0);
    kvissue(1);

    float o1[8][4], o2[8][4];
#pragma unroll
    for (int d = 0; d < 8; d++)
#pragma unroll
        for (int q = 0; q < 4; q++) { o1[d][q] = 0.f; o2[d][q] = 0.f; }
    float l1[2] = {0.f, 0.f}, l2[2] = {0.f, 0.f};   // per-thread partials

    const uint32_t a_off = (wm + (lane & 15)) * 128 + (lane >> 4) * 16;
    const uint32_t b_off = ((lane & 7) + ((lane >> 4) & 1) * 8) * 128
                         + ((lane >> 3) & 1) * 16;
    const uint32_t v_off = (lane & 15) * 128 + (lane >> 4) * 16;

    for (int kt = 0; kt < 16; kt++) {
        if (kt < 15)
            asm volatile("cp.async.wait_group 1;" ::: "memory");
        else
            asm volatile("cp.async.wait_group 0;" ::: "memory");
        __syncthreads();
        if (kt + 2 < 16) kvissue(kt + 2);

        const uint32_t stb = kv0 + (kt % 3) * KVST;

        uint32_t ph1[4][4], pl1[4][4], ph2[4][4], pl2[4][4];

#pragma unroll
        for (int br = 0; br < 2; br++) {
            const uint32_t sAh = sb + (br ? 2 : 0) * 16384;
            const uint32_t sAl = sAh + 16384;
            const uint32_t sBh = stb + (br ? 2 : 0) * 8192;
            const uint32_t sBl = sBh + 8192;
            float* l = br ? l2 : l1;

            // ---- S = Q K^T over 64 keys (3-product split) ----
            float sf[8][4];
#pragma unroll
            for (int nf = 0; nf < 8; nf++)
#pragma unroll
                for (int q = 0; q < 4; q++) sf[nf][q] = 0.f;
#pragma unroll
            for (int ks = 0; ks < 4; ks++) {
                uint32_t aH[4], aL[4];
                ldsm4(aH, sAh + swz(a_off + ks * 32));
                ldsm4(aL, sAl + swz(a_off + ks * 32));
#pragma unroll
                for (int g = 0; g < 4; g++) {
                    uint32_t bH[4], bL[4];
                    uint32_t off = swz(b_off + g * 2048 + ks * 32);
                    ldsm4(bH, sBh + off);
                    ldsm4(bL, sBl + off);
                    MMA_BF16(sf[2*g],   aH, bH);
                    MMA_BF16(sf[2*g],   aH, bL);
                    MMA_BF16(sf[2*g],   aL, bH);
                    MMA_BF16(sf[2*g+1], aH, bH + 2);
                    MMA_BF16(sf[2*g+1], aH, bL + 2);
                    MMA_BF16(sf[2*g+1], aL, bH + 2);
                }
            }

            // ---- P = 2^S ; accumulate per-thread l partials ----
            float p0 = 0.f, p1 = 0.f;
#pragma unroll
            for (int nf = 0; nf < 8; nf++) {
                sf[nf][0] = ex2(sf[nf][0]); p0 += sf[nf][0];
                sf[nf][1] = ex2(sf[nf][1]); p0 += sf[nf][1];
                sf[nf][2] = ex2(sf[nf][2]); p1 += sf[nf][2];
                sf[nf][3] = ex2(sf[nf][3]); p1 += sf[nf][3];
            }
            l[0] += p0; l[1] += p1;

            // ---- pack P fragments (bf16 hi/lo, A-layout) ----
            uint32_t (*ph)[4] = br ? ph2 : ph1;
            uint32_t (*pl)[4] = br ? pl2 : pl1;
#pragma unroll
            for (int kf = 0; kf < 4; kf++) {
                float* f0 = sf[2*kf];
                float* f1 = sf[2*kf+1];
                ph[kf][0] = pkhi(f0[0], f0[1]);
                ph[kf][1] = pkhi(f0[2], f0[3]);
                ph[kf][2] = pkhi(f1[0], f1[1]);
                ph[kf][3] = pkhi(f1[2], f1[3]);
                pl[kf][0] = pkbf2(trunclo(f0[0]), trunclo(f0[1]));
                pl[kf][1] = pkbf2(trunclo(f0[2]), trunclo(f0[3]));
                pl[kf][2] = pkbf2(trunclo(f1[0]), trunclo(f1[1]));
                pl[kf][3] = pkbf2(trunclo(f1[2]), trunclo(f1[3]));
            }
        }

        // ---- O += P V for both branches, V fragments loaded once ----
        const uint32_t sVh = stb + 4 * 8192;
        const uint32_t sVl = stb + 5 * 8192;
#pragma unroll
        for (int kf = 0; kf < 4; kf++) {
#pragma unroll
            for (int d2 = 0; d2 < 4; d2++) {
                uint32_t vH[4], vL[4];
                uint32_t off = swz(v_off + kf * 2048 + d2 * 32);
                ldsm4t(vH, sVh + off);
                ldsm4t(vL, sVl + off);
                MMA_BF16(o1[d2*2],   ph1[kf], vH);
                MMA_BF16(o1[d2*2],   ph1[kf], vL);
                MMA_BF16(o1[d2*2],   pl1[kf], vH);
                MMA_BF16(o1[d2*2+1], ph1[kf], vH + 2);
                MMA_BF16(o1[d2*2+1], ph1[kf], vL + 2);
                MMA_BF16(o1[d2*2+1], pl1[kf], vH + 2);
                MMA_BF16(o2[d2*2],   ph2[kf], vH);
                MMA_BF16(o2[d2*2],   ph2[kf], vL);
                MMA_BF16(o2[d2*2],   pl2[kf], vH);
                MMA_BF16(o2[d2*2+1], ph2[kf], vH + 2);
                MMA_BF16(o2[d2*2+1], ph2[kf], vL + 2);
                MMA_BF16(o2[d2*2+1], pl2[kf], vH + 2);
            }
        }
    }

    // ---- reduce l across quads (columns of each row) ----
#pragma unroll
    for (int off = 1; off <= 2; off <<= 1) {
        l1[0] += __shfl_xor_sync(0xffffffffu, l1[0], off);
        l1[1] += __shfl_xor_sync(0xffffffffu, l1[1], off);
        l2[0] += __shfl_xor_sync(0xffffffffu, l2[0], off);
        l2[1] += __shfl_xor_sync(0xffffffffu, l2[1], off);
    }

    // ---- epilogue: y = O1/l1 - softplus(lmb)·O2/l2 ----
    float cH = log1pf(__expf(lmb[h]));
    float i10 = 1.f / l1[0], i11 = 1.f / l1[1];
    float i20 = cH / l2[0],  i21 = cH / l2[1];
    const int er = lane >> 2, ec = (lane & 3) * 2;
#pragma unroll
    for (int d = 0; d < 8; d++) {
        size_t r0 = bh + (size_t)(qt * 128 + wm + er) * 64 + d * 8 + ec;
        size_t r1 = r0 + 8 * 64;
        float2 v0 = make_float2(o1[d][0] * i10 - o2[d][0] * i20,
                                o1[d][1] * i10 - o2[d][1] * i20);
        float2 v1 = make_float2(o1[d][2] * i11 - o2[d][2] * i21,
                                o1[d][3] * i11 - o2[d][3] * i21);
        *(float2*)(g_y + r0) = v0;
        *(float2*)(g_y + r1) = v1;
    }
}

// -------- GroupNorm per (b,h) over (T,HD); emits bf16 hi/lo split directly -
__global__ void groupnorm_kernel(const float* __restrict__ gn_w,
                                 const float* __restrict__ gn_b,
                                 __nv_bfloat16* __restrict__ AH,
                                 __nv_bfloat16* __restrict__ AL)
{
    __shared__ float rs[256], rq[256];
    const int bh = blockIdx.x;
    const float* src = g_y + (size_t)bh * TT * HD;
    const int tid = threadIdx.x;
    float s = 0.f, sq = 0.f;
    for (int i = tid; i < TT * HD; i += 256) {
        float v = src[i]; s += v; sq += v * v;
    }
    rs[tid] = s; rq[tid] = sq;
    __syncthreads();
    for (int off = 128; off > 0; off >>= 1) {
        if (tid < off) { rs[tid] += rs[tid + off]; rq[tid] += rq[tid + off]; }
        __syncthreads();
    }
    float mu  = rs[0] * (1.f / 65536.f);
    float var = rq[0] * (1.f / 65536.f) - mu * mu;
    float inv = rsqrtf(var + 1e-5f);
    int b = bh >> 4, h = bh & 15;
    for (int i = tid; i < TT * HD; i += 256) {
        int t = i >> 6, d = i & 63;
        float v = (src[i] - mu) * inv * gn_w[h * 64 + d] + gn_b[h * 64 + d];
        size_t o = (size_t)(b * TT + t) * DD + h * 64 + d;
        __nv_bfloat16 hi = __float2bfloat16(v);
        AH[o] = hi;
        AL[o] = __float2bfloat16(v - __bfloat162float(hi));
    }
}

// ---------------------------------------------------------------------------
extern "C" void kernel_launch(void* const* d_in, const int* in_sizes, int n_in,
                              void* d_out, int out_size)
{
    const float* x_q  = (const float*)d_in[0];
    const float* x_kv = (const float*)d_in[1];
    const float* Wq   = (const float*)d_in[2];
    const float* Wkv  = (const float*)d_in[3];
    const float* Wc   = (const float*)d_in[4];
    const float* qn1  = (const float*)d_in[5];
    const float* kn1  = (const float*)d_in[6];
    const float* qn2  = (const float*)d_in[7];
    const float* kn2  = (const float*)d_in[8];
    const float* gn_w = (const float*)d_in[9];
    const float* gn_b = (const float*)d_in[10];
    const float* lmb  = (const float*)d_in[11];
    float* out = (float*)d_out;
    (void)in_sizes; (void)n_in; (void)out_size;

    __nv_bfloat16 *AH, *AL, *BH, *BL;
    cudaGetSymbolAddress((void**)&AH, g_AH);
    cudaGetSymbolAddress((void**)&AL, g_AL);
    cudaGetSymbolAddress((void**)&BH, g_BH);
    cudaGetSymbolAddress((void**)&BL, g_BL);

    cudaFuncSetAttribute(mma_gemm<0>,
        cudaFuncAttributeMaxDynamicSharedMemorySize, MG_TOTAL);
    cudaFuncSetAttribute(mma_gemm<1>,
        cudaFuncAttributeMaxDynamicSharedMemorySize, MG_TOTAL);
    cudaFuncSetAttribute(mma_gemm<2>,
        cudaFuncAttributeMaxDynamicSharedMemorySize, MG_TOTAL);
    cudaFuncSetAttribute(attn_mma,
        cudaFuncAttributeMaxDynamicSharedMemorySize, AT_SMEM);

    // 1) q projections + fused per-head RMSNorm -> bf16 hi/lo head-major
    convA<<<4096, 256>>>(x_q, AH, AL);
    convBT<<<dim3(64, 32), dim3(32, 8)>>>(Wq, BH, BL, 1024, 2048);
    mma_gemm<1><<<dim3(16, 32), 256, MG_TOTAL>>>(AH, AL, BH, BL,
        (float*)0, qn1, qn2, 4096, 2048, 1024);
    // 2) kv projections + fused RMSNorm / V split
    convA<<<4096, 256>>>(x_kv, AH, AL);
    convBT<<<dim3(96, 32), dim3(32, 8)>>>(Wkv, BH, BL, 1024, 3072);
    mma_gemm<2><<<dim3(24, 32), 256, MG_TOTAL>>>(AH, AL, BH, BL,
        (float*)0, kn1, kn2, 4096, 3072, 1024);
    // 3) tensor-core differential flash attention (3-stage ring)
    attn_mma<<<dim3(8, 16, 4), 256, AT_SMEM>>>(lmb);
    // 4) GroupNorm + relayout + bf16 split (fused)
    groupnorm_kernel<<<64, 256>>>(gn_w, gn_b, AH, AL);
    // 5) out = yt @ Wc
    convBT<<<dim3(32, 32), dim3(32, 8)>>>(Wc, BH, BL, 1024, 1024);
    mma_gemm<0><<<dim3(8, 32), 256, MG_TOTAL>>>(AH, AL, BH, BL,
        out, (float*)0, (float*)0, 4096, 1024, 1024);
}